// round 1
// baseline (speedup 1.0000x reference)
#include <cuda_runtime.h>
#include <math.h>

#define BB 2
#define SS 2048
#define DIM 4096
#define NH 32
#define NKV 8
#define HD 128

// Scratch (device globals — no allocation allowed)
__device__ float g_q[(size_t)BB * SS * NH * HD];     // 64 MB
__device__ float g_k[(size_t)BB * SS * NKV * HD];    // 16 MB
__device__ float g_v[(size_t)BB * SS * NKV * HD];    // 16 MB
__device__ float g_attn[(size_t)BB * SS * NH * HD];  // 64 MB

// ---------------------------------------------------------------------------
// SGEMM: C[M,N] = A[M,K] @ B[K,N], all row-major fp32.
// 128x128 block tile, BK=8, 256 threads, 8x8 per thread.
// ---------------------------------------------------------------------------
__global__ __launch_bounds__(256) void sgemm128(
    const float* __restrict__ A, const float* __restrict__ Bm,
    float* __restrict__ C, int M, int N, int K)
{
    __shared__ float As[8][128];   // transposed: As[k][m]
    __shared__ float Bs[8][128];

    int tid = threadIdx.x;
    int aRow = tid >> 1;            // 0..127
    int aCol = (tid & 1) * 4;       // 0 or 4
    int bRow = tid >> 5;            // 0..7
    int bCol = (tid & 31) * 4;      // 0..124
    int tx = tid & 15, ty = tid >> 4;

    const float* Ab = A + (size_t)blockIdx.y * 128 * K;
    const float* Bb = Bm + (size_t)blockIdx.x * 128;

    float acc[8][8];
#pragma unroll
    for (int i = 0; i < 8; i++)
#pragma unroll
        for (int j = 0; j < 8; j++) acc[i][j] = 0.f;

    for (int k0 = 0; k0 < K; k0 += 8) {
        float4 av = *(const float4*)(Ab + (size_t)aRow * K + k0 + aCol);
        As[aCol + 0][aRow] = av.x;
        As[aCol + 1][aRow] = av.y;
        As[aCol + 2][aRow] = av.z;
        As[aCol + 3][aRow] = av.w;
        *(float4*)(&Bs[bRow][bCol]) =
            *(const float4*)(Bb + (size_t)(k0 + bRow) * N + bCol);
        __syncthreads();

#pragma unroll
        for (int kk = 0; kk < 8; kk++) {
            float ar[8], br[8];
            *(float4*)(ar)     = *(const float4*)(&As[kk][ty * 8]);
            *(float4*)(ar + 4) = *(const float4*)(&As[kk][ty * 8 + 4]);
            *(float4*)(br)     = *(const float4*)(&Bs[kk][tx * 8]);
            *(float4*)(br + 4) = *(const float4*)(&Bs[kk][tx * 8 + 4]);
#pragma unroll
            for (int i = 0; i < 8; i++)
#pragma unroll
                for (int j = 0; j < 8; j++)
                    acc[i][j] += ar[i] * br[j];
        }
        __syncthreads();
    }

#pragma unroll
    for (int i = 0; i < 8; i++) {
        size_t row = (size_t)blockIdx.y * 128 + ty * 8 + i;
        float* cp = C + row * N + blockIdx.x * 128 + tx * 8;
        *(float4*)(cp)     = make_float4(acc[i][0], acc[i][1], acc[i][2], acc[i][3]);
        *(float4*)(cp + 4) = make_float4(acc[i][4], acc[i][5], acc[i][6], acc[i][7]);
    }
}

// ---------------------------------------------------------------------------
// RoPE, in place, layout (b, s, h, d) with interleaved pairs (even, odd).
// ---------------------------------------------------------------------------
__global__ void rope_kernel(float* __restrict__ t,
                            const float* __restrict__ cosb,
                            const float* __restrict__ sinb,
                            int nh, int total)
{
    int idx = blockIdx.x * blockDim.x + threadIdx.x;
    if (idx >= total) return;
    int p = idx & 63;               // HD/2 = 64
    int tmp = idx >> 6;
    int h = tmp % nh; tmp /= nh;
    int s = tmp % SS;
    int b = tmp / SS;
    float c  = cosb[s * 64 + p];
    float sn = sinb[s * 64 + p];
    float* base = t + ((((size_t)b * SS + s) * nh + h) * HD) + 2 * p;
    float x0 = base[0], x1 = base[1];
    base[0] = x0 * c - x1 * sn;
    base[1] = x0 * sn + x1 * c;
}

// ---------------------------------------------------------------------------
// Flash attention (fp32, causal, GQA). One block = 64 query rows of one head.
// grid = (S/64, NH, B). 256 threads. Dynamic smem: Qs, Ks (aliased by Ps), Vs.
// ---------------------------------------------------------------------------
#define QSTR 132   // 128 + 4 pad (bank-conflict-free column reads)
#define PSTR 68    // 64 + 4 pad

__global__ __launch_bounds__(256) void attn_kernel(
    const float* __restrict__ Qg, const float* __restrict__ Kg,
    const float* __restrict__ Vg, float* __restrict__ Og)
{
    extern __shared__ float sm[];
    float* Qs = sm;                 // [64][QSTR]
    float* Ks = sm + 64 * QSTR;     // [64][QSTR], aliased by Ps [64][PSTR]
    float* Vs = sm + 2 * 64 * QSTR; // [64][QSTR]
    float* Ps = Ks;

    int qt = blockIdx.x, h = blockIdx.y, b = blockIdx.z;
    int g = h >> 2;                 // NH / NKV = 4
    int i0 = qt * 64;
    int tid = threadIdx.x;
    int tx = tid & 15, ty = tid >> 4;

    const float scale = 0.08838834764831845f;  // 1/sqrt(128)

    // Load Q tile (scaled)
    for (int t = tid; t < 64 * 32; t += 256) {
        int row = t >> 5;
        int c4 = (t & 31) << 2;
        float4 v = *(const float4*)(
            Qg + ((((size_t)b * SS + i0 + row) * NH + h) * HD + c4));
        v.x *= scale; v.y *= scale; v.z *= scale; v.w *= scale;
        *(float4*)(Qs + row * QSTR + c4) = v;
    }

    float m_i[4], l_i[4], O[4][8];
#pragma unroll
    for (int i = 0; i < 4; i++) {
        m_i[i] = -1e30f; l_i[i] = 0.f;
#pragma unroll
        for (int c = 0; c < 8; c++) O[i][c] = 0.f;
    }

    for (int jt = 0; jt <= qt; jt++) {
        int j0 = jt * 64;
        __syncthreads();  // prev PV done (and Q load on first iter)

        // Load K, V tiles
        for (int t = tid; t < 64 * 32; t += 256) {
            int row = t >> 5;
            int c4 = (t & 31) << 2;
            size_t goff = (((size_t)b * SS + j0 + row) * NKV + g) * HD + c4;
            *(float4*)(Ks + row * QSTR + c4) = *(const float4*)(Kg + goff);
            *(float4*)(Vs + row * QSTR + c4) = *(const float4*)(Vg + goff);
        }
        __syncthreads();

        // S tile = Qs @ Ks^T  (4x4 per thread)
        float acc[4][4];
#pragma unroll
        for (int i = 0; i < 4; i++)
#pragma unroll
            for (int j = 0; j < 4; j++) acc[i][j] = 0.f;

#pragma unroll 4
        for (int d = 0; d < HD; d += 4) {
            float4 qv[4], kv[4];
#pragma unroll
            for (int i = 0; i < 4; i++)
                qv[i] = *(const float4*)(Qs + (ty * 4 + i) * QSTR + d);
#pragma unroll
            for (int j = 0; j < 4; j++)
                kv[j] = *(const float4*)(Ks + (tx * 4 + j) * QSTR + d);
#pragma unroll
            for (int i = 0; i < 4; i++)
#pragma unroll
                for (int j = 0; j < 4; j++)
                    acc[i][j] += qv[i].x * kv[j].x + qv[i].y * kv[j].y
                               + qv[i].z * kv[j].z + qv[i].w * kv[j].w;
        }

        // Causal mask (only the diagonal tile can violate causality)
        if (jt == qt) {
#pragma unroll
            for (int i = 0; i < 4; i++) {
                int qi = ty * 4 + i;
#pragma unroll
                for (int j = 0; j < 4; j++)
                    if (tx * 4 + j > qi) acc[i][j] = -1e30f;
            }
        }

        __syncthreads();  // everyone done reading Ks before Ps overwrite

        // Online softmax per row (rows shared by 16 lanes in one half-warp)
#pragma unroll
        for (int i = 0; i < 4; i++) {
            float rmax = fmaxf(fmaxf(acc[i][0], acc[i][1]),
                               fmaxf(acc[i][2], acc[i][3]));
#pragma unroll
            for (int msk = 8; msk >= 1; msk >>= 1)
                rmax = fmaxf(rmax, __shfl_xor_sync(0xffffffffu, rmax, msk));
            float mnew = fmaxf(m_i[i], rmax);
            float alpha = expf(m_i[i] - mnew);
            float p0 = expf(acc[i][0] - mnew);
            float p1 = expf(acc[i][1] - mnew);
            float p2 = expf(acc[i][2] - mnew);
            float p3 = expf(acc[i][3] - mnew);
            float rsum = p0 + p1 + p2 + p3;
#pragma unroll
            for (int msk = 8; msk >= 1; msk >>= 1)
                rsum += __shfl_xor_sync(0xffffffffu, rsum, msk);
            l_i[i] = l_i[i] * alpha + rsum;
            m_i[i] = mnew;
#pragma unroll
            for (int c = 0; c < 8; c++) O[i][c] *= alpha;
            float* pr = Ps + (ty * 4 + i) * PSTR + tx * 4;
            pr[0] = p0; pr[1] = p1; pr[2] = p2; pr[3] = p3;
        }
        __syncthreads();

        // O += Ps @ Vs
#pragma unroll 4
        for (int j = 0; j < 64; j++) {
            float4 v0 = *(const float4*)(Vs + j * QSTR + tx * 8);
            float4 v1 = *(const float4*)(Vs + j * QSTR + tx * 8 + 4);
#pragma unroll
            for (int i = 0; i < 4; i++) {
                float pv = Ps[(ty * 4 + i) * PSTR + j];
                O[i][0] += pv * v0.x; O[i][1] += pv * v0.y;
                O[i][2] += pv * v0.z; O[i][3] += pv * v0.w;
                O[i][4] += pv * v1.x; O[i][5] += pv * v1.y;
                O[i][6] += pv * v1.z; O[i][7] += pv * v1.w;
            }
        }
    }

    // Epilogue: normalize and write to (b, s, h*HD + d) — GEMM-ready layout
#pragma unroll
    for (int i = 0; i < 4; i++) {
        float inv = 1.f / l_i[i];
        size_t row = (size_t)b * SS + i0 + ty * 4 + i;
        float* op = Og + row * (NH * HD) + h * HD + tx * 8;
        *(float4*)(op)     = make_float4(O[i][0] * inv, O[i][1] * inv,
                                         O[i][2] * inv, O[i][3] * inv);
        *(float4*)(op + 4) = make_float4(O[i][4] * inv, O[i][5] * inv,
                                         O[i][6] * inv, O[i][7] * inv);
    }
}

// ---------------------------------------------------------------------------
// Launch. Inputs (metadata order): x, start_pos, freqs_cos, freqs_sin, cache,
// mask, wq, wk, wv, wo. start_pos == 0 and cache is zero, so cache/mask are
// implemented analytically (causal mask, full-length K/V).
// ---------------------------------------------------------------------------
extern "C" void kernel_launch(void* const* d_in, const int* in_sizes, int n_in,
                              void* d_out, int out_size)
{
    const float* x  = (const float*)d_in[0];
    const float* fc = (const float*)d_in[2];
    const float* fs = (const float*)d_in[3];
    const float* wq = (const float*)d_in[6];
    const float* wk = (const float*)d_in[7];
    const float* wv = (const float*)d_in[8];
    const float* wo = (const float*)d_in[9];
    float* out = (float*)d_out;

    float *q, *k, *v, *attn;
    cudaGetSymbolAddress((void**)&q, g_q);
    cudaGetSymbolAddress((void**)&k, g_k);
    cudaGetSymbolAddress((void**)&v, g_v);
    cudaGetSymbolAddress((void**)&attn, g_attn);

    const int M = BB * SS;  // 4096

    // QKV projections
    sgemm128<<<dim3(NH * HD / 128, M / 128), 256>>>(x, wq, q, M, NH * HD, DIM);
    sgemm128<<<dim3(NKV * HD / 128, M / 128), 256>>>(x, wk, k, M, NKV * HD, DIM);
    sgemm128<<<dim3(NKV * HD / 128, M / 128), 256>>>(x, wv, v, M, NKV * HD, DIM);

    // RoPE on Q and K
    int qtot = BB * SS * NH * (HD / 2);
    int ktot = BB * SS * NKV * (HD / 2);
    rope_kernel<<<(qtot + 255) / 256, 256>>>(q, fc, fs, NH, qtot);
    rope_kernel<<<(ktot + 255) / 256, 256>>>(k, fc, fs, NKV, ktot);

    // Flash attention
    int smem = 3 * 64 * QSTR * (int)sizeof(float);  // 101376 B
    cudaFuncSetAttribute(attn_kernel,
                         cudaFuncAttributeMaxDynamicSharedMemorySize, smem);
    attn_kernel<<<dim3(SS / 64, NH, BB), 256, smem>>>(q, k, v, attn);

    // Output projection
    sgemm128<<<dim3(DIM / 128, M / 128), 256>>>(attn, wo, out, M, DIM, DIM);
}

// round 2
// speedup vs baseline: 2.0791x; 2.0791x over previous
#include <cuda_runtime.h>
#include <math.h>

#define BB 2
#define SS 2048
#define DIM 4096
#define NH 32
#define NKV 8
#define HD 128

// Scratch (device globals — no allocation allowed)
__device__ float g_q[(size_t)BB * SS * NH * HD];     // 64 MB
__device__ float g_k[(size_t)BB * SS * NKV * HD];    // 16 MB
__device__ float g_v[(size_t)BB * SS * NKV * HD];    // 16 MB
__device__ float g_attn[(size_t)BB * SS * NH * HD];  // 64 MB

// ---------------------------------------------------------------------------
// TF32 tensor-core GEMM: C[M,N] = A[M,K] @ B[K,N], row-major fp32 in/out.
// 128x128 block tile, BK=16, 256 threads (8 warps as 2m x 4n, 64x32 warp tile),
// cp.async double buffering, mma.sync.m16n8k8.tf32 with rna rounding.
// ---------------------------------------------------------------------------
#define ASTR 20    // A smem row stride (floats): 20*g mod 32 -> conflict-free frags
#define BSTR 136   // B smem row stride (floats): 136*k mod 32 = 8k -> conflict-free

__device__ __forceinline__ unsigned f2tf(float x) {
    unsigned r;
    asm("cvt.rna.tf32.f32 %0, %1;" : "=r"(r) : "f"(x));
    return r;
}

__device__ __forceinline__ void cpa16(void* dst, const void* src) {
    unsigned d = (unsigned)__cvta_generic_to_shared(dst);
    asm volatile("cp.async.cg.shared.global [%0], [%1], 16;\n" :: "r"(d), "l"(src));
}

__device__ __forceinline__ void mma_tf32(float* d, const unsigned* a, const unsigned* b) {
    asm volatile(
        "mma.sync.aligned.m16n8k8.row.col.f32.tf32.tf32.f32 "
        "{%0,%1,%2,%3}, {%4,%5,%6,%7}, {%8,%9}, {%0,%1,%2,%3};\n"
        : "+f"(d[0]), "+f"(d[1]), "+f"(d[2]), "+f"(d[3])
        : "r"(a[0]), "r"(a[1]), "r"(a[2]), "r"(a[3]), "r"(b[0]), "r"(b[1]));
}

__global__ __launch_bounds__(256) void gemm_tf32(
    const float* __restrict__ A, const float* __restrict__ Bm,
    float* __restrict__ C, int M, int N, int K)
{
    __shared__ float As[2][128 * ASTR];
    __shared__ float Bs[2][16 * BSTR];

    const int tid  = threadIdx.x;
    const int lane = tid & 31;
    const int warp = tid >> 5;
    const int g    = lane >> 2;   // groupID 0..7
    const int tg   = lane & 3;    // thread-in-group 0..3

    const int warpM = warp >> 2;  // 0..1
    const int warpN = warp & 3;   // 0..3
    const int mBase = warpM * 64;
    const int nBase = warpN * 32;

    const int bm = blockIdx.y * 128;
    const int bn = blockIdx.x * 128;

    // global staging indices
    const int aRow = tid >> 2;          // 0..63
    const int aCol = (tid & 3) * 4;     // 0,4,8,12
    const int bRow = tid >> 5;          // 0..7
    const int bCol = (tid & 31) * 4;    // 0..124

    const float* Ag  = A + (size_t)(bm + aRow) * K + aCol;
    const float* Ag2 = Ag + (size_t)64 * K;
    const float* Bg  = Bm + (size_t)bRow * N + bn + bCol;
    const float* Bg2 = Bg + (size_t)8 * N;

    float acc[4][4][4];
#pragma unroll
    for (int mt = 0; mt < 4; mt++)
#pragma unroll
        for (int nt = 0; nt < 4; nt++)
#pragma unroll
            for (int c = 0; c < 4; c++) acc[mt][nt][c] = 0.f;

    const int T = K / 16;

    // prologue: stage 0
    cpa16(&As[0][aRow * ASTR + aCol],        Ag);
    cpa16(&As[0][(aRow + 64) * ASTR + aCol], Ag2);
    cpa16(&Bs[0][bRow * BSTR + bCol],        Bg);
    cpa16(&Bs[0][(bRow + 8) * BSTR + bCol],  Bg2);
    asm volatile("cp.async.commit_group;\n");

    for (int t = 0; t < T; t++) {
        asm volatile("cp.async.wait_group 0;\n");
        __syncthreads();

        if (t + 1 < T) {
            int s1 = (t + 1) & 1;
            int k0 = (t + 1) * 16;
            cpa16(&As[s1][aRow * ASTR + aCol],        Ag + k0);
            cpa16(&As[s1][(aRow + 64) * ASTR + aCol], Ag2 + k0);
            cpa16(&Bs[s1][bRow * BSTR + bCol],        Bg + (size_t)k0 * N);
            cpa16(&Bs[s1][(bRow + 8) * BSTR + bCol],  Bg2 + (size_t)k0 * N);
            asm volatile("cp.async.commit_group;\n");
        }

        const int s = t & 1;
#pragma unroll
        for (int kk = 0; kk < 16; kk += 8) {
            unsigned a[4][4], b[4][2];
#pragma unroll
            for (int mt = 0; mt < 4; mt++) {
                int r = mBase + mt * 16 + g;
                a[mt][0] = f2tf(As[s][r * ASTR + kk + tg]);
                a[mt][1] = f2tf(As[s][(r + 8) * ASTR + kk + tg]);
                a[mt][2] = f2tf(As[s][r * ASTR + kk + tg + 4]);
                a[mt][3] = f2tf(As[s][(r + 8) * ASTR + kk + tg + 4]);
            }
#pragma unroll
            for (int nt = 0; nt < 4; nt++) {
                int c = nBase + nt * 8 + g;
                b[nt][0] = f2tf(Bs[s][(kk + tg) * BSTR + c]);
                b[nt][1] = f2tf(Bs[s][(kk + tg + 4) * BSTR + c]);
            }
#pragma unroll
            for (int mt = 0; mt < 4; mt++)
#pragma unroll
                for (int nt = 0; nt < 4; nt++)
                    mma_tf32(acc[mt][nt], a[mt], b[nt]);
        }
    }

    // epilogue
#pragma unroll
    for (int mt = 0; mt < 4; mt++) {
        int row0 = bm + mBase + mt * 16 + g;
#pragma unroll
        for (int nt = 0; nt < 4; nt++) {
            int col = bn + nBase + nt * 8 + 2 * tg;
            *(float2*)(C + (size_t)row0 * N + col) =
                make_float2(acc[mt][nt][0], acc[mt][nt][1]);
            *(float2*)(C + (size_t)(row0 + 8) * N + col) =
                make_float2(acc[mt][nt][2], acc[mt][nt][3]);
        }
    }
}

// ---------------------------------------------------------------------------
// RoPE, in place, layout (b, s, h, d) with interleaved pairs (even, odd).
// ---------------------------------------------------------------------------
__global__ void rope_kernel(float* __restrict__ t,
                            const float* __restrict__ cosb,
                            const float* __restrict__ sinb,
                            int nh, int total)
{
    int idx = blockIdx.x * blockDim.x + threadIdx.x;
    if (idx >= total) return;
    int p = idx & 63;               // HD/2 = 64
    int tmp = idx >> 6;
    int h = tmp % nh; tmp /= nh;
    int s = tmp % SS;
    int b = tmp / SS;
    float c  = cosb[s * 64 + p];
    float sn = sinb[s * 64 + p];
    float* base = t + ((((size_t)b * SS + s) * nh + h) * HD) + 2 * p;
    float x0 = base[0], x1 = base[1];
    base[0] = x0 * c - x1 * sn;
    base[1] = x0 * sn + x1 * c;
}

// ---------------------------------------------------------------------------
// Flash attention (fp32, causal, GQA). One block = 64 query rows of one head.
// grid = (S/64, NH, B). 256 threads. Dynamic smem: Qs, Ks (aliased by Ps), Vs.
// ---------------------------------------------------------------------------
#define QSTR 132   // 128 + 4 pad (bank-conflict-free column reads)
#define PSTR 68    // 64 + 4 pad

__global__ __launch_bounds__(256) void attn_kernel(
    const float* __restrict__ Qg, const float* __restrict__ Kg,
    const float* __restrict__ Vg, float* __restrict__ Og)
{
    extern __shared__ float sm[];
    float* Qs = sm;                 // [64][QSTR]
    float* Ks = sm + 64 * QSTR;     // [64][QSTR], aliased by Ps [64][PSTR]
    float* Vs = sm + 2 * 64 * QSTR; // [64][QSTR]
    float* Ps = Ks;

    int qt = blockIdx.x, h = blockIdx.y, b = blockIdx.z;
    int g = h >> 2;                 // NH / NKV = 4
    int i0 = qt * 64;
    int tid = threadIdx.x;
    int tx = tid & 15, ty = tid >> 4;

    const float scale = 0.08838834764831845f;  // 1/sqrt(128)

    // Load Q tile (scaled)
    for (int t = tid; t < 64 * 32; t += 256) {
        int row = t >> 5;
        int c4 = (t & 31) << 2;
        float4 v = *(const float4*)(
            Qg + ((((size_t)b * SS + i0 + row) * NH + h) * HD + c4));
        v.x *= scale; v.y *= scale; v.z *= scale; v.w *= scale;
        *(float4*)(Qs + row * QSTR + c4) = v;
    }

    float m_i[4], l_i[4], O[4][8];
#pragma unroll
    for (int i = 0; i < 4; i++) {
        m_i[i] = -1e30f; l_i[i] = 0.f;
#pragma unroll
        for (int c = 0; c < 8; c++) O[i][c] = 0.f;
    }

    for (int jt = 0; jt <= qt; jt++) {
        int j0 = jt * 64;
        __syncthreads();  // prev PV done (and Q load on first iter)

        // Load K, V tiles
        for (int t = tid; t < 64 * 32; t += 256) {
            int row = t >> 5;
            int c4 = (t & 31) << 2;
            size_t goff = (((size_t)b * SS + j0 + row) * NKV + g) * HD + c4;
            *(float4*)(Ks + row * QSTR + c4) = *(const float4*)(Kg + goff);
            *(float4*)(Vs + row * QSTR + c4) = *(const float4*)(Vg + goff);
        }
        __syncthreads();

        // S tile = Qs @ Ks^T  (4x4 per thread)
        float acc[4][4];
#pragma unroll
        for (int i = 0; i < 4; i++)
#pragma unroll
            for (int j = 0; j < 4; j++) acc[i][j] = 0.f;

#pragma unroll 4
        for (int d = 0; d < HD; d += 4) {
            float4 qv[4], kv[4];
#pragma unroll
            for (int i = 0; i < 4; i++)
                qv[i] = *(const float4*)(Qs + (ty * 4 + i) * QSTR + d);
#pragma unroll
            for (int j = 0; j < 4; j++)
                kv[j] = *(const float4*)(Ks + (tx * 4 + j) * QSTR + d);
#pragma unroll
            for (int i = 0; i < 4; i++)
#pragma unroll
                for (int j = 0; j < 4; j++)
                    acc[i][j] += qv[i].x * kv[j].x + qv[i].y * kv[j].y
                               + qv[i].z * kv[j].z + qv[i].w * kv[j].w;
        }

        // Causal mask (only the diagonal tile can violate causality)
        if (jt == qt) {
#pragma unroll
            for (int i = 0; i < 4; i++) {
                int qi = ty * 4 + i;
#pragma unroll
                for (int j = 0; j < 4; j++)
                    if (tx * 4 + j > qi) acc[i][j] = -1e30f;
            }
        }

        __syncthreads();  // everyone done reading Ks before Ps overwrite

        // Online softmax per row (rows shared by 16 lanes in one half-warp)
#pragma unroll
        for (int i = 0; i < 4; i++) {
            float rmax = fmaxf(fmaxf(acc[i][0], acc[i][1]),
                               fmaxf(acc[i][2], acc[i][3]));
#pragma unroll
            for (int msk = 8; msk >= 1; msk >>= 1)
                rmax = fmaxf(rmax, __shfl_xor_sync(0xffffffffu, rmax, msk));
            float mnew = fmaxf(m_i[i], rmax);
            float alpha = expf(m_i[i] - mnew);
            float p0 = expf(acc[i][0] - mnew);
            float p1 = expf(acc[i][1] - mnew);
            float p2 = expf(acc[i][2] - mnew);
            float p3 = expf(acc[i][3] - mnew);
            float rsum = p0 + p1 + p2 + p3;
#pragma unroll
            for (int msk = 8; msk >= 1; msk >>= 1)
                rsum += __shfl_xor_sync(0xffffffffu, rsum, msk);
            l_i[i] = l_i[i] * alpha + rsum;
            m_i[i] = mnew;
#pragma unroll
            for (int c = 0; c < 8; c++) O[i][c] *= alpha;
            float* pr = Ps + (ty * 4 + i) * PSTR + tx * 4;
            pr[0] = p0; pr[1] = p1; pr[2] = p2; pr[3] = p3;
        }
        __syncthreads();

        // O += Ps @ Vs
#pragma unroll 4
        for (int j = 0; j < 64; j++) {
            float4 v0 = *(const float4*)(Vs + j * QSTR + tx * 8);
            float4 v1 = *(const float4*)(Vs + j * QSTR + tx * 8 + 4);
#pragma unroll
            for (int i = 0; i < 4; i++) {
                float pv = Ps[(ty * 4 + i) * PSTR + j];
                O[i][0] += pv * v0.x; O[i][1] += pv * v0.y;
                O[i][2] += pv * v0.z; O[i][3] += pv * v0.w;
                O[i][4] += pv * v1.x; O[i][5] += pv * v1.y;
                O[i][6] += pv * v1.z; O[i][7] += pv * v1.w;
            }
        }
    }

    // Epilogue: normalize and write to (b, s, h*HD + d) — GEMM-ready layout
#pragma unroll
    for (int i = 0; i < 4; i++) {
        float inv = 1.f / l_i[i];
        size_t row = (size_t)b * SS + i0 + ty * 4 + i;
        float* op = Og + row * (NH * HD) + h * HD + tx * 8;
        *(float4*)(op)     = make_float4(O[i][0] * inv, O[i][1] * inv,
                                         O[i][2] * inv, O[i][3] * inv);
        *(float4*)(op + 4) = make_float4(O[i][4] * inv, O[i][5] * inv,
                                         O[i][6] * inv, O[i][7] * inv);
    }
}

// ---------------------------------------------------------------------------
// Launch. Inputs (metadata order): x, start_pos, freqs_cos, freqs_sin, cache,
// mask, wq, wk, wv, wo. start_pos == 0 and cache is zero, so cache/mask are
// implemented analytically (causal mask, full-length K/V).
// ---------------------------------------------------------------------------
extern "C" void kernel_launch(void* const* d_in, const int* in_sizes, int n_in,
                              void* d_out, int out_size)
{
    const float* x  = (const float*)d_in[0];
    const float* fc = (const float*)d_in[2];
    const float* fs = (const float*)d_in[3];
    const float* wq = (const float*)d_in[6];
    const float* wk = (const float*)d_in[7];
    const float* wv = (const float*)d_in[8];
    const float* wo = (const float*)d_in[9];
    float* out = (float*)d_out;

    float *q, *k, *v, *attn;
    cudaGetSymbolAddress((void**)&q, g_q);
    cudaGetSymbolAddress((void**)&k, g_k);
    cudaGetSymbolAddress((void**)&v, g_v);
    cudaGetSymbolAddress((void**)&attn, g_attn);

    const int M = BB * SS;  // 4096

    // QKV projections (tf32 tensor cores)
    gemm_tf32<<<dim3(NH * HD / 128, M / 128), 256>>>(x, wq, q, M, NH * HD, DIM);
    gemm_tf32<<<dim3(NKV * HD / 128, M / 128), 256>>>(x, wk, k, M, NKV * HD, DIM);
    gemm_tf32<<<dim3(NKV * HD / 128, M / 128), 256>>>(x, wv, v, M, NKV * HD, DIM);

    // RoPE on Q and K
    int qtot = BB * SS * NH * (HD / 2);
    int ktot = BB * SS * NKV * (HD / 2);
    rope_kernel<<<(qtot + 255) / 256, 256>>>(q, fc, fs, NH, qtot);
    rope_kernel<<<(ktot + 255) / 256, 256>>>(k, fc, fs, NKV, ktot);

    // Flash attention
    int smem = 3 * 64 * QSTR * (int)sizeof(float);  // 101376 B
    cudaFuncSetAttribute(attn_kernel,
                         cudaFuncAttributeMaxDynamicSharedMemorySize, smem);
    attn_kernel<<<dim3(SS / 64, NH, BB), 256, smem>>>(q, k, v, attn);

    // Output projection (tf32 tensor cores)
    gemm_tf32<<<dim3(DIM / 128, M / 128), 256>>>(attn, wo, out, M, DIM, DIM);
}

// round 3
// speedup vs baseline: 2.1164x; 1.0179x over previous
#include <cuda_runtime.h>
#include <cuda_bf16.h>
#include <math.h>

#define BB 2
#define SS 2048
#define DIM 4096
#define NH 32
#define NKV 8
#define HD 128

// Scratch (device globals — no allocation allowed)
__device__ float g_q[(size_t)BB * SS * NH * HD];     // 64 MB
__device__ float g_k[(size_t)BB * SS * NKV * HD];    // 16 MB
__device__ float g_v[(size_t)BB * SS * NKV * HD];    // 16 MB
__device__ float g_attn[(size_t)BB * SS * NH * HD];  // 64 MB

__device__ __forceinline__ unsigned f2tf(float x) {
    unsigned r;
    asm("cvt.rna.tf32.f32 %0, %1;" : "=r"(r) : "f"(x));
    return r;
}

__device__ __forceinline__ void cpa16(void* dst, const void* src) {
    unsigned d = (unsigned)__cvta_generic_to_shared(dst);
    asm volatile("cp.async.cg.shared.global [%0], [%1], 16;\n" :: "r"(d), "l"(src));
}

__device__ __forceinline__ void mma_tf32(float* d, const unsigned* a, const unsigned* b) {
    asm volatile(
        "mma.sync.aligned.m16n8k8.row.col.f32.tf32.tf32.f32 "
        "{%0,%1,%2,%3}, {%4,%5,%6,%7}, {%8,%9}, {%0,%1,%2,%3};\n"
        : "+f"(d[0]), "+f"(d[1]), "+f"(d[2]), "+f"(d[3])
        : "r"(a[0]), "r"(a[1]), "r"(a[2]), "r"(a[3]), "r"(b[0]), "r"(b[1]));
}

// ---------------------------------------------------------------------------
// TF32 tensor-core GEMM: C[M,N] = A[M,K] @ B[K,N], row-major fp32 in/out.
// ---------------------------------------------------------------------------
#define ASTR 20
#define BSTR 136

__global__ __launch_bounds__(256) void gemm_tf32(
    const float* __restrict__ A, const float* __restrict__ Bm,
    float* __restrict__ C, int M, int N, int K)
{
    __shared__ float As[2][128 * ASTR];
    __shared__ float Bs[2][16 * BSTR];

    const int tid  = threadIdx.x;
    const int lane = tid & 31;
    const int warp = tid >> 5;
    const int g    = lane >> 2;
    const int tg   = lane & 3;

    const int warpM = warp >> 2;
    const int warpN = warp & 3;
    const int mBase = warpM * 64;
    const int nBase = warpN * 32;

    const int bm = blockIdx.y * 128;
    const int bn = blockIdx.x * 128;

    const int aRow = tid >> 2;
    const int aCol = (tid & 3) * 4;
    const int bRow = tid >> 5;
    const int bCol = (tid & 31) * 4;

    const float* Ag  = A + (size_t)(bm + aRow) * K + aCol;
    const float* Ag2 = Ag + (size_t)64 * K;
    const float* Bg  = Bm + (size_t)bRow * N + bn + bCol;
    const float* Bg2 = Bg + (size_t)8 * N;

    float acc[4][4][4];
#pragma unroll
    for (int mt = 0; mt < 4; mt++)
#pragma unroll
        for (int nt = 0; nt < 4; nt++)
#pragma unroll
            for (int c = 0; c < 4; c++) acc[mt][nt][c] = 0.f;

    const int T = K / 16;

    cpa16(&As[0][aRow * ASTR + aCol],        Ag);
    cpa16(&As[0][(aRow + 64) * ASTR + aCol], Ag2);
    cpa16(&Bs[0][bRow * BSTR + bCol],        Bg);
    cpa16(&Bs[0][(bRow + 8) * BSTR + bCol],  Bg2);
    asm volatile("cp.async.commit_group;\n");

    for (int t = 0; t < T; t++) {
        asm volatile("cp.async.wait_group 0;\n");
        __syncthreads();

        if (t + 1 < T) {
            int s1 = (t + 1) & 1;
            int k0 = (t + 1) * 16;
            cpa16(&As[s1][aRow * ASTR + aCol],        Ag + k0);
            cpa16(&As[s1][(aRow + 64) * ASTR + aCol], Ag2 + k0);
            cpa16(&Bs[s1][bRow * BSTR + bCol],        Bg + (size_t)k0 * N);
            cpa16(&Bs[s1][(bRow + 8) * BSTR + bCol],  Bg2 + (size_t)k0 * N);
            asm volatile("cp.async.commit_group;\n");
        }

        const int s = t & 1;
#pragma unroll
        for (int kk = 0; kk < 16; kk += 8) {
            unsigned a[4][4], b[4][2];
#pragma unroll
            for (int mt = 0; mt < 4; mt++) {
                int r = mBase + mt * 16 + g;
                a[mt][0] = f2tf(As[s][r * ASTR + kk + tg]);
                a[mt][1] = f2tf(As[s][(r + 8) * ASTR + kk + tg]);
                a[mt][2] = f2tf(As[s][r * ASTR + kk + tg + 4]);
                a[mt][3] = f2tf(As[s][(r + 8) * ASTR + kk + tg + 4]);
            }
#pragma unroll
            for (int nt = 0; nt < 4; nt++) {
                int c = nBase + nt * 8 + g;
                b[nt][0] = f2tf(Bs[s][(kk + tg) * BSTR + c]);
                b[nt][1] = f2tf(Bs[s][(kk + tg + 4) * BSTR + c]);
            }
#pragma unroll
            for (int mt = 0; mt < 4; mt++)
#pragma unroll
                for (int nt = 0; nt < 4; nt++)
                    mma_tf32(acc[mt][nt], a[mt], b[nt]);
        }
    }

#pragma unroll
    for (int mt = 0; mt < 4; mt++) {
        int row0 = bm + mBase + mt * 16 + g;
#pragma unroll
        for (int nt = 0; nt < 4; nt++) {
            int col = bn + nBase + nt * 8 + 2 * tg;
            *(float2*)(C + (size_t)row0 * N + col) =
                make_float2(acc[mt][nt][0], acc[mt][nt][1]);
            *(float2*)(C + (size_t)(row0 + 8) * N + col) =
                make_float2(acc[mt][nt][2], acc[mt][nt][3]);
        }
    }
}

// ---------------------------------------------------------------------------
// RoPE, in place.
// ---------------------------------------------------------------------------
__global__ void rope_kernel(float* __restrict__ t,
                            const float* __restrict__ cosb,
                            const float* __restrict__ sinb,
                            int nh, int total)
{
    int idx = blockIdx.x * blockDim.x + threadIdx.x;
    if (idx >= total) return;
    int p = idx & 63;
    int tmp = idx >> 6;
    int h = tmp % nh; tmp /= nh;
    int s = tmp % SS;
    int b = tmp / SS;
    float c  = cosb[s * 64 + p];
    float sn = sinb[s * 64 + p];
    float* base = t + ((((size_t)b * SS + s) * nh + h) * HD) + 2 * p;
    float x0 = base[0], x1 = base[1];
    base[0] = x0 * c - x1 * sn;
    base[1] = x0 * sn + x1 * c;
}

// ---------------------------------------------------------------------------
// Tensor-core flash attention (causal, GQA).
// Block = 128 q rows x 1 head. 8 warps x 16 rows. 64-wide KV tiles.
// QK^T in 3-term split tf32 (~fp32 accuracy), PV in plain tf32.
// Smem: Qb(u32) + Qsmall(bf16) + Kb(u32) + Ksmall(bf16) + V(tf32) + P(tf32).
// ---------------------------------------------------------------------------
#define BM 128
#define BN 64
#define QST 132   // (4g+tg) mod 32 unique -> conflict-free fragments
#define PST 66

#define ATTN_SMEM 219648

__global__ __launch_bounds__(256) void attn_mma(
    const float* __restrict__ Qg, const float* __restrict__ Kg,
    const float* __restrict__ Vg, float* __restrict__ Og)
{
    extern __shared__ char smraw[];
    unsigned*       Qb  = (unsigned*)(smraw);                 // [128][132] u32
    unsigned short* Qsm = (unsigned short*)(smraw + 67584);   // [128][132] bf16
    unsigned*       Kb  = (unsigned*)(smraw + 101376);        // [64][132] u32
    unsigned short* Ksm = (unsigned short*)(smraw + 135168);  // [64][132] bf16
    unsigned*       Vt  = (unsigned*)(smraw + 152064);        // [64][132] tf32
    unsigned*       Pt  = (unsigned*)(smraw + 185856);        // [128][66] tf32

    const int tid  = threadIdx.x;
    const int lane = tid & 31;
    const int warp = tid >> 5;
    const int g    = lane >> 2;
    const int tg   = lane & 3;

    const int qt = (int)gridDim.x - 1 - (int)blockIdx.x;  // heavy blocks first
    const int h  = blockIdx.y;
    const int b  = blockIdx.z;
    const int kvh = h >> 2;
    const int i0 = qt * BM;
    const int rw = warp * 16;

    const float scale = 0.08838834764831845f;  // 1/sqrt(128)

    // --- Load Q tile: scale, split big(tf32 u32) + small(bf16) ---
    for (int t = tid; t < BM * 32; t += 256) {
        int row = t >> 5;
        int c4  = (t & 31) << 2;
        float4 q = *(const float4*)(
            Qg + ((((size_t)b * SS + i0 + row) * NH + h) * HD + c4));
        float vals[4] = {q.x * scale, q.y * scale, q.z * scale, q.w * scale};
#pragma unroll
        for (int j = 0; j < 4; j++) {
            unsigned bg = f2tf(vals[j]);
            float smv = vals[j] - __uint_as_float(bg);
            Qb[row * QST + c4 + j]  = bg;
            Qsm[row * QST + c4 + j] = (unsigned short)(__bfloat16_as_ushort(__float2bfloat16(smv)));
        }
    }

    float O[16][4];
#pragma unroll
    for (int nt = 0; nt < 16; nt++)
#pragma unroll
        for (int c = 0; c < 4; c++) O[nt][c] = 0.f;
    float m0 = -1e30f, m1 = -1e30f, l0 = 0.f, l1 = 0.f;

    const int jt_max = (i0 + BM - 1) >> 6;  // inclusive

    for (int jt = 0; jt <= jt_max; jt++) {
        int j0 = jt * BN;
        __syncthreads();  // prev iter done with K/V smem

        // --- Load K (split) and V (tf32) tiles ---
        for (int t = tid; t < BN * 32; t += 256) {
            int row = t >> 5;
            int c4  = (t & 31) << 2;
            size_t goff = (((size_t)b * SS + j0 + row) * NKV + kvh) * HD + c4;
            float4 kv = *(const float4*)(Kg + goff);
            float kvals[4] = {kv.x, kv.y, kv.z, kv.w};
#pragma unroll
            for (int j = 0; j < 4; j++) {
                unsigned bg = f2tf(kvals[j]);
                float smv = kvals[j] - __uint_as_float(bg);
                Kb[row * QST + c4 + j]  = bg;
                Ksm[row * QST + c4 + j] = (unsigned short)(__bfloat16_as_ushort(__float2bfloat16(smv)));
            }
            float4 vv = *(const float4*)(Vg + goff);
            Vt[row * QST + c4 + 0] = f2tf(vv.x);
            Vt[row * QST + c4 + 1] = f2tf(vv.y);
            Vt[row * QST + c4 + 2] = f2tf(vv.z);
            Vt[row * QST + c4 + 3] = f2tf(vv.w);
        }
        __syncthreads();

        // Warp fully masked for this tile? (all its rows < all tile cols)
        if (j0 > i0 + rw + 15) continue;

        // --- S = Q K^T (3-term split tf32) ---
        float sacc[8][4];
#pragma unroll
        for (int nt = 0; nt < 8; nt++)
#pragma unroll
            for (int c = 0; c < 4; c++) sacc[nt][c] = 0.f;

        const int r0 = rw + g, r1 = rw + g + 8;
#pragma unroll
        for (int kk = 0; kk < HD; kk += 8) {
            unsigned ab[4], asl[4];
            ab[0] = Qb[r0 * QST + kk + tg];
            ab[1] = Qb[r1 * QST + kk + tg];
            ab[2] = Qb[r0 * QST + kk + tg + 4];
            ab[3] = Qb[r1 * QST + kk + tg + 4];
            asl[0] = ((unsigned)Qsm[r0 * QST + kk + tg]) << 16;
            asl[1] = ((unsigned)Qsm[r1 * QST + kk + tg]) << 16;
            asl[2] = ((unsigned)Qsm[r0 * QST + kk + tg + 4]) << 16;
            asl[3] = ((unsigned)Qsm[r1 * QST + kk + tg + 4]) << 16;
#pragma unroll
            for (int nt = 0; nt < 8; nt++) {
                int c = nt * 8 + g;
                unsigned bb[2], bs[2];
                bb[0] = Kb[c * QST + kk + tg];
                bb[1] = Kb[c * QST + kk + tg + 4];
                bs[0] = ((unsigned)Ksm[c * QST + kk + tg]) << 16;
                bs[1] = ((unsigned)Ksm[c * QST + kk + tg + 4]) << 16;
                mma_tf32(sacc[nt], ab,  bb);
                mma_tf32(sacc[nt], asl, bb);
                mma_tf32(sacc[nt], ab,  bs);
            }
        }

        // --- Causal mask (elementwise, only near diagonal) ---
        const int gr0 = i0 + r0, gr1 = i0 + r1;
        if (j0 + BN - 1 > i0 + rw) {
#pragma unroll
            for (int nt = 0; nt < 8; nt++) {
                int col = j0 + nt * 8 + 2 * tg;
                if (col     > gr0) sacc[nt][0] = -1e30f;
                if (col + 1 > gr0) sacc[nt][1] = -1e30f;
                if (col     > gr1) sacc[nt][2] = -1e30f;
                if (col + 1 > gr1) sacc[nt][3] = -1e30f;
            }
        }

        // --- Online softmax (rows gr0, gr1 per thread; 4 lanes share a row) ---
        float mx0 = -1e30f, mx1 = -1e30f;
#pragma unroll
        for (int nt = 0; nt < 8; nt++) {
            mx0 = fmaxf(mx0, fmaxf(sacc[nt][0], sacc[nt][1]));
            mx1 = fmaxf(mx1, fmaxf(sacc[nt][2], sacc[nt][3]));
        }
        mx0 = fmaxf(mx0, __shfl_xor_sync(0xffffffffu, mx0, 1));
        mx0 = fmaxf(mx0, __shfl_xor_sync(0xffffffffu, mx0, 2));
        mx1 = fmaxf(mx1, __shfl_xor_sync(0xffffffffu, mx1, 1));
        mx1 = fmaxf(mx1, __shfl_xor_sync(0xffffffffu, mx1, 2));

        float mn0 = fmaxf(m0, mx0), mn1 = fmaxf(m1, mx1);
        float al0 = __expf(m0 - mn0), al1 = __expf(m1 - mn1);
        float rs0 = 0.f, rs1 = 0.f;
#pragma unroll
        for (int nt = 0; nt < 8; nt++) {
            float p0 = __expf(sacc[nt][0] - mn0);
            float p1 = __expf(sacc[nt][1] - mn0);
            float p2 = __expf(sacc[nt][2] - mn1);
            float p3 = __expf(sacc[nt][3] - mn1);
            rs0 += p0 + p1;
            rs1 += p2 + p3;
            int colb = nt * 8 + 2 * tg;
            *(uint2*)&Pt[r0 * PST + colb] = make_uint2(f2tf(p0), f2tf(p1));
            *(uint2*)&Pt[r1 * PST + colb] = make_uint2(f2tf(p2), f2tf(p3));
        }
        rs0 += __shfl_xor_sync(0xffffffffu, rs0, 1);
        rs0 += __shfl_xor_sync(0xffffffffu, rs0, 2);
        rs1 += __shfl_xor_sync(0xffffffffu, rs1, 1);
        rs1 += __shfl_xor_sync(0xffffffffu, rs1, 2);
        m0 = mn0; m1 = mn1;
        l0 = l0 * al0 + rs0;
        l1 = l1 * al1 + rs1;

#pragma unroll
        for (int nt = 0; nt < 16; nt++) {
            O[nt][0] *= al0; O[nt][1] *= al0;
            O[nt][2] *= al1; O[nt][3] *= al1;
        }
        __syncwarp();

        // --- O += P V (tf32) ---
#pragma unroll
        for (int kk = 0; kk < BN; kk += 8) {
            unsigned pa[4];
            pa[0] = Pt[r0 * PST + kk + tg];
            pa[1] = Pt[r1 * PST + kk + tg];
            pa[2] = Pt[r0 * PST + kk + tg + 4];
            pa[3] = Pt[r1 * PST + kk + tg + 4];
#pragma unroll
            for (int nt = 0; nt < 16; nt++) {
                unsigned vb[2];
                vb[0] = Vt[(kk + tg) * QST + nt * 8 + g];
                vb[1] = Vt[(kk + tg + 4) * QST + nt * 8 + g];
                mma_tf32(O[nt], pa, vb);
            }
        }
    }

    // --- Epilogue: normalize, write (b, s, h*HD+d) layout ---
    float inv0 = 1.f / l0, inv1 = 1.f / l1;
    size_t row0 = (size_t)b * SS + i0 + rw + g;
    size_t row1 = row0 + 8;
#pragma unroll
    for (int nt = 0; nt < 16; nt++) {
        int col = h * HD + nt * 8 + 2 * tg;
        *(float2*)(Og + row0 * (NH * HD) + col) =
            make_float2(O[nt][0] * inv0, O[nt][1] * inv0);
        *(float2*)(Og + row1 * (NH * HD) + col) =
            make_float2(O[nt][2] * inv1, O[nt][3] * inv1);
    }
}

// ---------------------------------------------------------------------------
// Launch. Inputs: x, start_pos, freqs_cos, freqs_sin, cache, mask, wq, wk, wv, wo.
// start_pos == 0, cache zero -> causal mask analytic, full-length K/V.
// ---------------------------------------------------------------------------
extern "C" void kernel_launch(void* const* d_in, const int* in_sizes, int n_in,
                              void* d_out, int out_size)
{
    const float* x  = (const float*)d_in[0];
    const float* fc = (const float*)d_in[2];
    const float* fs = (const float*)d_in[3];
    const float* wq = (const float*)d_in[6];
    const float* wk = (const float*)d_in[7];
    const float* wv = (const float*)d_in[8];
    const float* wo = (const float*)d_in[9];
    float* out = (float*)d_out;

    float *q, *k, *v, *attn;
    cudaGetSymbolAddress((void**)&q, g_q);
    cudaGetSymbolAddress((void**)&k, g_k);
    cudaGetSymbolAddress((void**)&v, g_v);
    cudaGetSymbolAddress((void**)&attn, g_attn);

    const int M = BB * SS;  // 4096

    gemm_tf32<<<dim3(NH * HD / 128, M / 128), 256>>>(x, wq, q, M, NH * HD, DIM);
    gemm_tf32<<<dim3(NKV * HD / 128, M / 128), 256>>>(x, wk, k, M, NKV * HD, DIM);
    gemm_tf32<<<dim3(NKV * HD / 128, M / 128), 256>>>(x, wv, v, M, NKV * HD, DIM);

    int qtot = BB * SS * NH * (HD / 2);
    int ktot = BB * SS * NKV * (HD / 2);
    rope_kernel<<<(qtot + 255) / 256, 256>>>(q, fc, fs, NH, qtot);
    rope_kernel<<<(ktot + 255) / 256, 256>>>(k, fc, fs, NKV, ktot);

    cudaFuncSetAttribute(attn_mma,
                         cudaFuncAttributeMaxDynamicSharedMemorySize, ATTN_SMEM);
    attn_mma<<<dim3(SS / BM, NH, BB), 256, ATTN_SMEM>>>(q, k, v, attn);

    gemm_tf32<<<dim3(DIM / 128, M / 128), 256>>>(attn, wo, out, M, DIM, DIM);
}

// round 6
// speedup vs baseline: 3.5242x; 1.6652x over previous
#include <cuda_runtime.h>
#include <cuda_bf16.h>
#include <math.h>

#define BB 2
#define SS 2048
#define DIM 4096
#define NH 32
#define NKV 8
#define HD 128

// Scratch (device globals — no allocation allowed)
__device__ float g_q[(size_t)BB * SS * NH * HD];
__device__ float g_k[(size_t)BB * SS * NKV * HD];
__device__ float g_v[(size_t)BB * SS * NKV * HD];
__device__ float g_attn[(size_t)BB * SS * NH * HD];
// Pre-rounded (tf32) copies
__device__ float g_xr[(size_t)BB * SS * DIM];
__device__ float g_wqr[(size_t)DIM * NH * HD];
__device__ float g_wkr[(size_t)DIM * NKV * HD];
__device__ float g_wvr[(size_t)DIM * NKV * HD];
__device__ float g_wor[(size_t)NH * HD * DIM];

__device__ __forceinline__ unsigned f2tf(float x) {
    unsigned r;
    asm("cvt.rna.tf32.f32 %0, %1;" : "=r"(r) : "f"(x));
    return r;
}

__device__ __forceinline__ void cpa16(void* dst, const void* src) {
    unsigned d = (unsigned)__cvta_generic_to_shared(dst);
    asm volatile("cp.async.cg.shared.global [%0], [%1], 16;\n" :: "r"(d), "l"(src));
}

__device__ __forceinline__ void mma_tf32(float* d, const unsigned* a, const unsigned* b) {
    asm volatile(
        "mma.sync.aligned.m16n8k8.row.col.f32.tf32.tf32.f32 "
        "{%0,%1,%2,%3}, {%4,%5,%6,%7}, {%8,%9}, {%0,%1,%2,%3};\n"
        : "+f"(d[0]), "+f"(d[1]), "+f"(d[2]), "+f"(d[3])
        : "r"(a[0]), "r"(a[1]), "r"(a[2]), "r"(a[3]), "r"(b[0]), "r"(b[1]));
}

// ---------------------------------------------------------------------------
// Pre-round fp32 -> tf32 bit pattern (rna), 4 elems/thread.
// ---------------------------------------------------------------------------
__global__ void round_tf32_kernel(const float* __restrict__ src,
                                  float* __restrict__ dst, int n4)
{
    int i = (blockIdx.x * blockDim.x + threadIdx.x) * 4;
    if (i >= n4) return;
    float4 v = *(const float4*)(src + i);
    float4 o;
    o.x = __uint_as_float(f2tf(v.x));
    o.y = __uint_as_float(f2tf(v.y));
    o.z = __uint_as_float(f2tf(v.z));
    o.w = __uint_as_float(f2tf(v.w));
    *(float4*)(dst + i) = o;
}

// ---------------------------------------------------------------------------
// TF32 tensor-core GEMM: C = A @ B, row-major. Inputs pre-rounded to tf32,
// so fragment loads are plain LDS (no CVT in the hot loop).
// ---------------------------------------------------------------------------
#define ASTR 20
#define BSTR 136

__global__ __launch_bounds__(256) void gemm_tf32(
    const float* __restrict__ A, const float* __restrict__ Bm,
    float* __restrict__ C, int M, int N, int K)
{
    __shared__ float As[2][128 * ASTR];
    __shared__ float Bs[2][16 * BSTR];

    const int tid  = threadIdx.x;
    const int lane = tid & 31;
    const int warp = tid >> 5;
    const int g    = lane >> 2;
    const int tg   = lane & 3;

    const int warpM = warp >> 2;
    const int warpN = warp & 3;
    const int mBase = warpM * 64;
    const int nBase = warpN * 32;

    const int bm = blockIdx.y * 128;
    const int bn = blockIdx.x * 128;

    const int aRow = tid >> 2;
    const int aCol = (tid & 3) * 4;
    const int bRow = tid >> 5;
    const int bCol = (tid & 31) * 4;

    const float* Ag  = A + (size_t)(bm + aRow) * K + aCol;
    const float* Ag2 = Ag + (size_t)64 * K;
    const float* Bg  = Bm + (size_t)bRow * N + bn + bCol;
    const float* Bg2 = Bg + (size_t)8 * N;

    float acc[4][4][4];
#pragma unroll
    for (int mt = 0; mt < 4; mt++)
#pragma unroll
        for (int nt = 0; nt < 4; nt++)
#pragma unroll
            for (int c = 0; c < 4; c++) acc[mt][nt][c] = 0.f;

    const int T = K / 16;

    cpa16(&As[0][aRow * ASTR + aCol],        Ag);
    cpa16(&As[0][(aRow + 64) * ASTR + aCol], Ag2);
    cpa16(&Bs[0][bRow * BSTR + bCol],        Bg);
    cpa16(&Bs[0][(bRow + 8) * BSTR + bCol],  Bg2);
    asm volatile("cp.async.commit_group;\n");

    for (int t = 0; t < T; t++) {
        asm volatile("cp.async.wait_group 0;\n");
        __syncthreads();

        if (t + 1 < T) {
            int s1 = (t + 1) & 1;
            int k0 = (t + 1) * 16;
            cpa16(&As[s1][aRow * ASTR + aCol],        Ag + k0);
            cpa16(&As[s1][(aRow + 64) * ASTR + aCol], Ag2 + k0);
            cpa16(&Bs[s1][bRow * BSTR + bCol],        Bg + (size_t)k0 * N);
            cpa16(&Bs[s1][(bRow + 8) * BSTR + bCol],  Bg2 + (size_t)k0 * N);
            asm volatile("cp.async.commit_group;\n");
        }

        const int s = t & 1;
#pragma unroll
        for (int kk = 0; kk < 16; kk += 8) {
            unsigned a[4][4], b[4][2];
#pragma unroll
            for (int mt = 0; mt < 4; mt++) {
                int r = mBase + mt * 16 + g;
                a[mt][0] = __float_as_uint(As[s][r * ASTR + kk + tg]);
                a[mt][1] = __float_as_uint(As[s][(r + 8) * ASTR + kk + tg]);
                a[mt][2] = __float_as_uint(As[s][r * ASTR + kk + tg + 4]);
                a[mt][3] = __float_as_uint(As[s][(r + 8) * ASTR + kk + tg + 4]);
            }
#pragma unroll
            for (int nt = 0; nt < 4; nt++) {
                int c = nBase + nt * 8 + g;
                b[nt][0] = __float_as_uint(Bs[s][(kk + tg) * BSTR + c]);
                b[nt][1] = __float_as_uint(Bs[s][(kk + tg + 4) * BSTR + c]);
            }
#pragma unroll
            for (int mt = 0; mt < 4; mt++)
#pragma unroll
                for (int nt = 0; nt < 4; nt++)
                    mma_tf32(acc[mt][nt], a[mt], b[nt]);
        }
    }

#pragma unroll
    for (int mt = 0; mt < 4; mt++) {
        int row0 = bm + mBase + mt * 16 + g;
#pragma unroll
        for (int nt = 0; nt < 4; nt++) {
            int col = bn + nBase + nt * 8 + 2 * tg;
            *(float2*)(C + (size_t)row0 * N + col) =
                make_float2(acc[mt][nt][0], acc[mt][nt][1]);
            *(float2*)(C + (size_t)(row0 + 8) * N + col) =
                make_float2(acc[mt][nt][2], acc[mt][nt][3]);
        }
    }
}

// ---------------------------------------------------------------------------
// RoPE, in place.
// ---------------------------------------------------------------------------
__global__ void rope_kernel(float* __restrict__ t,
                            const float* __restrict__ cosb,
                            const float* __restrict__ sinb,
                            int nh, int total)
{
    int idx = blockIdx.x * blockDim.x + threadIdx.x;
    if (idx >= total) return;
    int p = idx & 63;
    int tmp = idx >> 6;
    int h = tmp % nh; tmp /= nh;
    int s = tmp % SS;
    int b = tmp / SS;
    float c  = cosb[s * 64 + p];
    float sn = sinb[s * 64 + p];
    float* base = t + ((((size_t)b * SS + s) * nh + h) * HD) + 2 * p;
    float x0 = base[0], x1 = base[1];
    base[0] = x0 * c - x1 * sn;
    base[1] = x0 * sn + x1 * c;
}

// ---------------------------------------------------------------------------
// Tensor-core flash attention, 512 threads / 16 warps.
// Block = 128 q rows x 1 head. Warp pair p covers rows p*16..p*16+15:
//   warp half 0: S cols 0..31 of the 64-wide kv tile, O cols 0..63
//   warp half 1: S cols 32..63,                       O cols 64..127
// Softmax max/sum combined across the pair via smem + named barrier.
// QK^T: 3-term split tf32 (~fp32 accuracy). PV: plain tf32.
// ---------------------------------------------------------------------------
#define BM 128
#define BN 64
#define QST 132   // Q/K row stride: bank = 4g+tg (unique)
#define VST 136   // V row stride: bank = 8tg+g (unique)
#define PST 68    // P row stride: bank = 4g+tg (unique)

// smem offsets (bytes)
#define OFF_QB   0
#define OFF_QSM  67584
#define OFF_KB   101376
#define OFF_KSM  135168
#define OFF_VT   152064
#define OFF_PT   186880
#define OFF_MAXB 221696
#define OFF_SUMB 222720
#define ATTN_SMEM 223744

__device__ __forceinline__ void barpair(int id) {
    asm volatile("bar.sync %0, %1;" :: "r"(id), "r"(64) : "memory");
}

__global__ __launch_bounds__(512) void attn_mma(
    const float* __restrict__ Qg, const float* __restrict__ Kg,
    const float* __restrict__ Vg, float* __restrict__ Og)
{
    extern __shared__ char smraw[];
    unsigned*       Qb   = (unsigned*)(smraw + OFF_QB);    // [128][132]
    unsigned short* Qsm  = (unsigned short*)(smraw + OFF_QSM);
    unsigned*       Kb   = (unsigned*)(smraw + OFF_KB);    // [64][132]
    unsigned short* Ksm  = (unsigned short*)(smraw + OFF_KSM);
    unsigned*       Vt   = (unsigned*)(smraw + OFF_VT);    // [64][136]
    unsigned*       Pt   = (unsigned*)(smraw + OFF_PT);    // [128][68]
    float*          maxb = (float*)(smraw + OFF_MAXB);     // [2][128]
    float*          sumb = (float*)(smraw + OFF_SUMB);     // [2][128]

    const int tid  = threadIdx.x;
    const int lane = tid & 31;
    const int warp = tid >> 5;
    const int g    = lane >> 2;
    const int tg   = lane & 3;

    const int pair = warp >> 1;       // 0..7
    const int half = warp & 1;        // 0..1
    const int rw   = pair * 16;
    const int scb  = half * 32;       // S col base within tile
    const int ocb  = half * 64;       // O col base within HD

    const int qt = (int)gridDim.x - 1 - (int)blockIdx.x;
    const int h  = blockIdx.y;
    const int b  = blockIdx.z;
    const int kvh = h >> 2;
    const int i0 = qt * BM;

    const float scale = 0.08838834764831845f;  // 1/sqrt(128)

    // --- Load Q: scale, split big(tf32) + small(bf16) ---
    for (int t = tid; t < BM * 32; t += 512) {
        int row = t >> 5;
        int c4  = (t & 31) << 2;
        float4 q = *(const float4*)(
            Qg + ((((size_t)b * SS + i0 + row) * NH + h) * HD + c4));
        float vals[4] = {q.x * scale, q.y * scale, q.z * scale, q.w * scale};
#pragma unroll
        for (int j = 0; j < 4; j++) {
            unsigned bg = f2tf(vals[j]);
            float smv = vals[j] - __uint_as_float(bg);
            Qb[row * QST + c4 + j]  = bg;
            Qsm[row * QST + c4 + j] =
                (unsigned short)__bfloat16_as_ushort(__float2bfloat16(smv));
        }
    }

    float O[8][4];
#pragma unroll
    for (int nt = 0; nt < 8; nt++)
#pragma unroll
        for (int c = 0; c < 4; c++) O[nt][c] = 0.f;
    float m0 = -1e30f, m1 = -1e30f, l0 = 0.f, l1 = 0.f;

    const int r0 = rw + g, r1 = rw + g + 8;
    const int jt_max = (i0 + BM - 1) >> 6;

    for (int jt = 0; jt <= jt_max; jt++) {
        int j0 = jt * BN;
        __syncthreads();  // prev iter done with K/V smem

        // --- Load K (split) and V (tf32) ---
        for (int t = tid; t < BN * 32; t += 512) {
            int row = t >> 5;
            int c4  = (t & 31) << 2;
            size_t goff = (((size_t)b * SS + j0 + row) * NKV + kvh) * HD + c4;
            float4 kv = *(const float4*)(Kg + goff);
            float kvals[4] = {kv.x, kv.y, kv.z, kv.w};
#pragma unroll
            for (int j = 0; j < 4; j++) {
                unsigned bg = f2tf(kvals[j]);
                float smv = kvals[j] - __uint_as_float(bg);
                Kb[row * QST + c4 + j]  = bg;
                Ksm[row * QST + c4 + j] =
                    (unsigned short)__bfloat16_as_ushort(__float2bfloat16(smv));
            }
            float4 vv = *(const float4*)(Vg + goff);
            Vt[row * VST + c4 + 0] = f2tf(vv.x);
            Vt[row * VST + c4 + 1] = f2tf(vv.y);
            Vt[row * VST + c4 + 2] = f2tf(vv.z);
            Vt[row * VST + c4 + 3] = f2tf(vv.w);
        }
        __syncthreads();

        // Whole warp-pair masked out?
        if (j0 > i0 + rw + 15) continue;

        // --- S = Q K^T over this warp's 32 cols (3-term split tf32) ---
        float sacc[4][4];
#pragma unroll
        for (int nt = 0; nt < 4; nt++)
#pragma unroll
            for (int c = 0; c < 4; c++) sacc[nt][c] = 0.f;

#pragma unroll
        for (int kk = 0; kk < HD; kk += 8) {
            unsigned ab[4], asl[4];
            ab[0] = Qb[r0 * QST + kk + tg];
            ab[1] = Qb[r1 * QST + kk + tg];
            ab[2] = Qb[r0 * QST + kk + tg + 4];
            ab[3] = Qb[r1 * QST + kk + tg + 4];
            asl[0] = ((unsigned)Qsm[r0 * QST + kk + tg]) << 16;
            asl[1] = ((unsigned)Qsm[r1 * QST + kk + tg]) << 16;
            asl[2] = ((unsigned)Qsm[r0 * QST + kk + tg + 4]) << 16;
            asl[3] = ((unsigned)Qsm[r1 * QST + kk + tg + 4]) << 16;
#pragma unroll
            for (int nt = 0; nt < 4; nt++) {
                int c = scb + nt * 8 + g;
                unsigned bb[2], bs[2];
                bb[0] = Kb[c * QST + kk + tg];
                bb[1] = Kb[c * QST + kk + tg + 4];
                bs[0] = ((unsigned)Ksm[c * QST + kk + tg]) << 16;
                bs[1] = ((unsigned)Ksm[c * QST + kk + tg + 4]) << 16;
                mma_tf32(sacc[nt], ab,  bb);
                mma_tf32(sacc[nt], asl, bb);
                mma_tf32(sacc[nt], ab,  bs);
            }
        }

        // --- Causal mask ---
        const int gr0 = i0 + r0, gr1 = i0 + r1;
        if (j0 + BN - 1 > i0 + rw) {
#pragma unroll
            for (int nt = 0; nt < 4; nt++) {
                int col = j0 + scb + nt * 8 + 2 * tg;
                if (col     > gr0) sacc[nt][0] = -1e30f;
                if (col + 1 > gr0) sacc[nt][1] = -1e30f;
                if (col     > gr1) sacc[nt][2] = -1e30f;
                if (col + 1 > gr1) sacc[nt][3] = -1e30f;
            }
        }

        // --- Pair-wide row max ---
        float mx0 = -1e30f, mx1 = -1e30f;
#pragma unroll
        for (int nt = 0; nt < 4; nt++) {
            mx0 = fmaxf(mx0, fmaxf(sacc[nt][0], sacc[nt][1]));
            mx1 = fmaxf(mx1, fmaxf(sacc[nt][2], sacc[nt][3]));
        }
        mx0 = fmaxf(mx0, __shfl_xor_sync(0xffffffffu, mx0, 1));
        mx0 = fmaxf(mx0, __shfl_xor_sync(0xffffffffu, mx0, 2));
        mx1 = fmaxf(mx1, __shfl_xor_sync(0xffffffffu, mx1, 1));
        mx1 = fmaxf(mx1, __shfl_xor_sync(0xffffffffu, mx1, 2));
        if (tg == 0) {
            maxb[half * 128 + r0] = mx0;
            maxb[half * 128 + r1] = mx1;
        }
        barpair(1 + pair);
        mx0 = fmaxf(mx0, maxb[(half ^ 1) * 128 + r0]);
        mx1 = fmaxf(mx1, maxb[(half ^ 1) * 128 + r1]);

        float mn0 = fmaxf(m0, mx0), mn1 = fmaxf(m1, mx1);
        float al0 = __expf(m0 - mn0), al1 = __expf(m1 - mn1);

        // --- exp, store P, pair-wide row sum ---
        float rs0 = 0.f, rs1 = 0.f;
#pragma unroll
        for (int nt = 0; nt < 4; nt++) {
            float p0 = __expf(sacc[nt][0] - mn0);
            float p1 = __expf(sacc[nt][1] - mn0);
            float p2 = __expf(sacc[nt][2] - mn1);
            float p3 = __expf(sacc[nt][3] - mn1);
            rs0 += p0 + p1;
            rs1 += p2 + p3;
            int colb = scb + nt * 8 + 2 * tg;
            *(uint2*)&Pt[r0 * PST + colb] = make_uint2(f2tf(p0), f2tf(p1));
            *(uint2*)&Pt[r1 * PST + colb] = make_uint2(f2tf(p2), f2tf(p3));
        }
        rs0 += __shfl_xor_sync(0xffffffffu, rs0, 1);
        rs0 += __shfl_xor_sync(0xffffffffu, rs0, 2);
        rs1 += __shfl_xor_sync(0xffffffffu, rs1, 1);
        rs1 += __shfl_xor_sync(0xffffffffu, rs1, 2);
        if (tg == 0) {
            sumb[half * 128 + r0] = rs0;
            sumb[half * 128 + r1] = rs1;
        }
        barpair(1 + pair);
        rs0 += sumb[(half ^ 1) * 128 + r0];
        rs1 += sumb[(half ^ 1) * 128 + r1];

        m0 = mn0; m1 = mn1;
        l0 = l0 * al0 + rs0;
        l1 = l1 * al1 + rs1;

#pragma unroll
        for (int nt = 0; nt < 8; nt++) {
            O[nt][0] *= al0; O[nt][1] *= al0;
            O[nt][2] *= al1; O[nt][3] *= al1;
        }

        // --- O += P V over this warp's 64 output cols ---
#pragma unroll
        for (int kk = 0; kk < BN; kk += 8) {
            unsigned pa[4];
            pa[0] = Pt[r0 * PST + kk + tg];
            pa[1] = Pt[r1 * PST + kk + tg];
            pa[2] = Pt[r0 * PST + kk + tg + 4];
            pa[3] = Pt[r1 * PST + kk + tg + 4];
#pragma unroll
            for (int nt = 0; nt < 8; nt++) {
                int oc = ocb + nt * 8 + g;
                unsigned vb[2];
                vb[0] = Vt[(kk + tg) * VST + oc];
                vb[1] = Vt[(kk + tg + 4) * VST + oc];
                mma_tf32(O[nt], pa, vb);
            }
        }
    }

    // --- Epilogue: normalize, round to tf32 (feeds wo GEMM), write ---
    float inv0 = 1.f / l0, inv1 = 1.f / l1;
    size_t row0 = (size_t)b * SS + i0 + rw + g;
    size_t row1 = row0 + 8;
#pragma unroll
    for (int nt = 0; nt < 8; nt++) {
        int col = h * HD + ocb + nt * 8 + 2 * tg;
        *(float2*)(Og + row0 * (NH * HD) + col) = make_float2(
            __uint_as_float(f2tf(O[nt][0] * inv0)),
            __uint_as_float(f2tf(O[nt][1] * inv0)));
        *(float2*)(Og + row1 * (NH * HD) + col) = make_float2(
            __uint_as_float(f2tf(O[nt][2] * inv1)),
            __uint_as_float(f2tf(O[nt][3] * inv1)));
    }
}

// ---------------------------------------------------------------------------
// Launch.
// ---------------------------------------------------------------------------
extern "C" void kernel_launch(void* const* d_in, const int* in_sizes, int n_in,
                              void* d_out, int out_size)
{
    const float* x  = (const float*)d_in[0];
    const float* fc = (const float*)d_in[2];
    const float* fs = (const float*)d_in[3];
    const float* wq = (const float*)d_in[6];
    const float* wk = (const float*)d_in[7];
    const float* wv = (const float*)d_in[8];
    const float* wo = (const float*)d_in[9];
    float* out = (float*)d_out;

    float *q, *k, *v, *attn, *xr, *wqr, *wkr, *wvr, *wor;
    cudaGetSymbolAddress((void**)&q, g_q);
    cudaGetSymbolAddress((void**)&k, g_k);
    cudaGetSymbolAddress((void**)&v, g_v);
    cudaGetSymbolAddress((void**)&attn, g_attn);
    cudaGetSymbolAddress((void**)&xr, g_xr);
    cudaGetSymbolAddress((void**)&wqr, g_wqr);
    cudaGetSymbolAddress((void**)&wkr, g_wkr);
    cudaGetSymbolAddress((void**)&wvr, g_wvr);
    cudaGetSymbolAddress((void**)&wor, g_wor);

    const int M = BB * SS;  // 4096

    // Pre-round inputs to tf32 (rna) once; GEMMs then skip CVT entirely.
    int nx = BB * SS * DIM;          // 16.7M
    int nq = DIM * NH * HD;          // 16.7M
    int nk = DIM * NKV * HD;         // 4.2M
    round_tf32_kernel<<<nx / 1024, 256>>>(x, xr, nx);
    round_tf32_kernel<<<nq / 1024, 256>>>(wq, wqr, nq);
    round_tf32_kernel<<<nk / 1024, 256>>>(wk, wkr, nk);
    round_tf32_kernel<<<nk / 1024, 256>>>(wv, wvr, nk);
    round_tf32_kernel<<<nq / 1024, 256>>>(wo, wor, nq);

    gemm_tf32<<<dim3(NH * HD / 128, M / 128), 256>>>(xr, wqr, q, M, NH * HD, DIM);
    gemm_tf32<<<dim3(NKV * HD / 128, M / 128), 256>>>(xr, wkr, k, M, NKV * HD, DIM);
    gemm_tf32<<<dim3(NKV * HD / 128, M / 128), 256>>>(xr, wvr, v, M, NKV * HD, DIM);

    int qtot = BB * SS * NH * (HD / 2);
    int ktot = BB * SS * NKV * (HD / 2);
    rope_kernel<<<(qtot + 255) / 256, 256>>>(q, fc, fs, NH, qtot);
    rope_kernel<<<(ktot + 255) / 256, 256>>>(k, fc, fs, NKV, ktot);

    cudaFuncSetAttribute(attn_mma,
                         cudaFuncAttributeMaxDynamicSharedMemorySize, ATTN_SMEM);
    attn_mma<<<dim3(SS / BM, NH, BB), 512, ATTN_SMEM>>>(q, k, v, attn);

    gemm_tf32<<<dim3(DIM / 128, M / 128), 256>>>(attn, wor, out, M, DIM, DIM);
}

// round 8
// speedup vs baseline: 3.5888x; 1.0183x over previous
#include <cuda_runtime.h>
#include <cuda_bf16.h>
#include <math.h>

#define BB 2
#define SS 2048
#define DIM 4096
#define NH 32
#define NKV 8
#define HD 128

// Scratch (device globals — no allocation allowed)
__device__ float g_q[(size_t)BB * SS * NH * HD];
__device__ float g_k[(size_t)BB * SS * NKV * HD];
__device__ float g_v[(size_t)BB * SS * NKV * HD];
__device__ float g_attn[(size_t)BB * SS * NH * HD];
// Pre-rounded (tf32) copies
__device__ float g_xr[(size_t)BB * SS * DIM];
__device__ float g_wqr[(size_t)DIM * NH * HD];
__device__ float g_wkr[(size_t)DIM * NKV * HD];
__device__ float g_wvr[(size_t)DIM * NKV * HD];
__device__ float g_wor[(size_t)NH * HD * DIM];

__device__ __forceinline__ unsigned f2tf(float x) {
    unsigned r;
    asm("cvt.rna.tf32.f32 %0, %1;" : "=r"(r) : "f"(x));
    return r;
}

__device__ __forceinline__ void cpa16(void* dst, const void* src) {
    unsigned d = (unsigned)__cvta_generic_to_shared(dst);
    asm volatile("cp.async.cg.shared.global [%0], [%1], 16;\n" :: "r"(d), "l"(src));
}

__device__ __forceinline__ void mma_tf32(float* d, const unsigned* a, const unsigned* b) {
    asm volatile(
        "mma.sync.aligned.m16n8k8.row.col.f32.tf32.tf32.f32 "
        "{%0,%1,%2,%3}, {%4,%5,%6,%7}, {%8,%9}, {%0,%1,%2,%3};\n"
        : "+f"(d[0]), "+f"(d[1]), "+f"(d[2]), "+f"(d[3])
        : "r"(a[0]), "r"(a[1]), "r"(a[2]), "r"(a[3]), "r"(b[0]), "r"(b[1]));
}

// ---------------------------------------------------------------------------
// Pre-round fp32 -> tf32 bit pattern (rna), 4 elems/thread.
// ---------------------------------------------------------------------------
__global__ void round_tf32_kernel(const float* __restrict__ src,
                                  float* __restrict__ dst, int n4)
{
    int i = (blockIdx.x * blockDim.x + threadIdx.x) * 4;
    if (i >= n4) return;
    float4 v = *(const float4*)(src + i);
    float4 o;
    o.x = __uint_as_float(f2tf(v.x));
    o.y = __uint_as_float(f2tf(v.y));
    o.z = __uint_as_float(f2tf(v.z));
    o.w = __uint_as_float(f2tf(v.w));
    *(float4*)(dst + i) = o;
}

// ---------------------------------------------------------------------------
// TF32 tensor-core GEMM: C = A @ B, row-major, inputs pre-rounded to tf32.
// 128x128 CTA tile, BK=16, 256 threads, 8 warps (2m x 4n, 64x32 warp tile).
// 4-stage cp.async pipeline, prefetch distance 3 (wait_group 2) so L2/DRAM
// latency is fully hidden; inner loop is pure LDS + HMMA.
// ---------------------------------------------------------------------------
#define ASTR 20
#define BSTR 136
#define GSTG 4
#define ASZ (128 * ASTR)          // floats per A stage
#define BSZ (16 * BSTR)           // floats per B stage
#define GEMM_SMEM (GSTG * (ASZ + BSZ) * 4)   // 75,776 bytes

__global__ __launch_bounds__(256) void gemm_tf32(
    const float* __restrict__ A, const float* __restrict__ Bm,
    float* __restrict__ C, int M, int N, int K)
{
    extern __shared__ float smf[];
    float* As = smf;               // [4][ASZ]
    float* Bs = smf + GSTG * ASZ;  // [4][BSZ]

    const int tid  = threadIdx.x;
    const int lane = tid & 31;
    const int warp = tid >> 5;
    const int g    = lane >> 2;
    const int tg   = lane & 3;

    const int warpM = warp >> 2;
    const int warpN = warp & 3;
    const int mBase = warpM * 64;
    const int nBase = warpN * 32;

    const int bm = blockIdx.y * 128;
    const int bn = blockIdx.x * 128;

    const int aRow = tid >> 2;
    const int aCol = (tid & 3) * 4;
    const int bRow = tid >> 5;
    const int bCol = (tid & 31) * 4;

    const float* Ag  = A + (size_t)(bm + aRow) * K + aCol;
    const float* Ag2 = Ag + (size_t)64 * K;
    const float* Bg  = Bm + (size_t)bRow * N + bn + bCol;
    const float* Bg2 = Bg + (size_t)8 * N;

    float acc[4][4][4];
#pragma unroll
    for (int mt = 0; mt < 4; mt++)
#pragma unroll
        for (int nt = 0; nt < 4; nt++)
#pragma unroll
            for (int c = 0; c < 4; c++) acc[mt][nt][c] = 0.f;

    const int T = K / 16;

    // Prologue: fill 3 stages
#pragma unroll
    for (int p = 0; p < GSTG - 1; p++) {
        if (p < T) {
            float* Ad = As + p * ASZ;
            float* Bd = Bs + p * BSZ;
            int k0 = p * 16;
            cpa16(&Ad[aRow * ASTR + aCol],        Ag + k0);
            cpa16(&Ad[(aRow + 64) * ASTR + aCol], Ag2 + k0);
            cpa16(&Bd[bRow * BSTR + bCol],        Bg + (size_t)k0 * N);
            cpa16(&Bd[(bRow + 8) * BSTR + bCol],  Bg2 + (size_t)k0 * N);
        }
        asm volatile("cp.async.commit_group;\n");
    }

    for (int t = 0; t < T; t++) {
        asm volatile("cp.async.wait_group %0;\n" :: "n"(GSTG - 2));
        __syncthreads();

        // Prefetch stage t+3 (buffer reuse is safe: the barrier above proves
        // every warp finished compute of iteration t-1, the last reader of
        // buffer (t+3)&3).
        if (t + GSTG - 1 < T) {
            int s1 = (t + GSTG - 1) & (GSTG - 1);
            int k0 = (t + GSTG - 1) * 16;
            float* Ad = As + s1 * ASZ;
            float* Bd = Bs + s1 * BSZ;
            cpa16(&Ad[aRow * ASTR + aCol],        Ag + k0);
            cpa16(&Ad[(aRow + 64) * ASTR + aCol], Ag2 + k0);
            cpa16(&Bd[bRow * BSTR + bCol],        Bg + (size_t)k0 * N);
            cpa16(&Bd[(bRow + 8) * BSTR + bCol],  Bg2 + (size_t)k0 * N);
        }
        asm volatile("cp.async.commit_group;\n");

        const float* Ac = As + (t & (GSTG - 1)) * ASZ;
        const float* Bc = Bs + (t & (GSTG - 1)) * BSZ;
#pragma unroll
        for (int kk = 0; kk < 16; kk += 8) {
            unsigned a[4][4], b[4][2];
#pragma unroll
            for (int mt = 0; mt < 4; mt++) {
                int r = mBase + mt * 16 + g;
                a[mt][0] = __float_as_uint(Ac[r * ASTR + kk + tg]);
                a[mt][1] = __float_as_uint(Ac[(r + 8) * ASTR + kk + tg]);
                a[mt][2] = __float_as_uint(Ac[r * ASTR + kk + tg + 4]);
                a[mt][3] = __float_as_uint(Ac[(r + 8) * ASTR + kk + tg + 4]);
            }
#pragma unroll
            for (int nt = 0; nt < 4; nt++) {
                int c = nBase + nt * 8 + g;
                b[nt][0] = __float_as_uint(Bc[(kk + tg) * BSTR + c]);
                b[nt][1] = __float_as_uint(Bc[(kk + tg + 4) * BSTR + c]);
            }
#pragma unroll
            for (int mt = 0; mt < 4; mt++)
#pragma unroll
                for (int nt = 0; nt < 4; nt++)
                    mma_tf32(acc[mt][nt], a[mt], b[nt]);
        }
    }

#pragma unroll
    for (int mt = 0; mt < 4; mt++) {
        int row0 = bm + mBase + mt * 16 + g;
#pragma unroll
        for (int nt = 0; nt < 4; nt++) {
            int col = bn + nBase + nt * 8 + 2 * tg;
            *(float2*)(C + (size_t)row0 * N + col) =
                make_float2(acc[mt][nt][0], acc[mt][nt][1]);
            *(float2*)(C + (size_t)(row0 + 8) * N + col) =
                make_float2(acc[mt][nt][2], acc[mt][nt][3]);
        }
    }
}

// ---------------------------------------------------------------------------
// RoPE, in place.
// ---------------------------------------------------------------------------
__global__ void rope_kernel(float* __restrict__ t,
                            const float* __restrict__ cosb,
                            const float* __restrict__ sinb,
                            int nh, int total)
{
    int idx = blockIdx.x * blockDim.x + threadIdx.x;
    if (idx >= total) return;
    int p = idx & 63;
    int tmp = idx >> 6;
    int h = tmp % nh; tmp /= nh;
    int s = tmp % SS;
    int b = tmp / SS;
    float c  = cosb[s * 64 + p];
    float sn = sinb[s * 64 + p];
    float* base = t + ((((size_t)b * SS + s) * nh + h) * HD) + 2 * p;
    float x0 = base[0], x1 = base[1];
    base[0] = x0 * c - x1 * sn;
    base[1] = x0 * sn + x1 * c;
}

// ---------------------------------------------------------------------------
// Tensor-core flash attention, 512 threads / 16 warps (round-6 version).
// ---------------------------------------------------------------------------
#define BM 128
#define BN 64
#define QST 132
#define VST 136
#define PST 68

#define OFF_QB   0
#define OFF_QSM  67584
#define OFF_KB   101376
#define OFF_KSM  135168
#define OFF_VT   152064
#define OFF_PT   186880
#define OFF_MAXB 221696
#define OFF_SUMB 222720
#define ATTN_SMEM 223744

__device__ __forceinline__ void barpair(int id) {
    asm volatile("bar.sync %0, %1;" :: "r"(id), "r"(64) : "memory");
}

__global__ __launch_bounds__(512) void attn_mma(
    const float* __restrict__ Qg, const float* __restrict__ Kg,
    const float* __restrict__ Vg, float* __restrict__ Og)
{
    extern __shared__ char smraw[];
    unsigned*       Qb   = (unsigned*)(smraw + OFF_QB);
    unsigned short* Qsm  = (unsigned short*)(smraw + OFF_QSM);
    unsigned*       Kb   = (unsigned*)(smraw + OFF_KB);
    unsigned short* Ksm  = (unsigned short*)(smraw + OFF_KSM);
    unsigned*       Vt   = (unsigned*)(smraw + OFF_VT);
    unsigned*       Pt   = (unsigned*)(smraw + OFF_PT);
    float*          maxb = (float*)(smraw + OFF_MAXB);
    float*          sumb = (float*)(smraw + OFF_SUMB);

    const int tid  = threadIdx.x;
    const int lane = tid & 31;
    const int warp = tid >> 5;
    const int g    = lane >> 2;
    const int tg   = lane & 3;

    const int pair = warp >> 1;
    const int half = warp & 1;
    const int rw   = pair * 16;
    const int scb  = half * 32;
    const int ocb  = half * 64;

    const int qt = (int)gridDim.x - 1 - (int)blockIdx.x;
    const int h  = blockIdx.y;
    const int b  = blockIdx.z;
    const int kvh = h >> 2;
    const int i0 = qt * BM;

    const float scale = 0.08838834764831845f;

    for (int t = tid; t < BM * 32; t += 512) {
        int row = t >> 5;
        int c4  = (t & 31) << 2;
        float4 q = *(const float4*)(
            Qg + ((((size_t)b * SS + i0 + row) * NH + h) * HD + c4));
        float vals[4] = {q.x * scale, q.y * scale, q.z * scale, q.w * scale};
#pragma unroll
        for (int j = 0; j < 4; j++) {
            unsigned bg = f2tf(vals[j]);
            float smv = vals[j] - __uint_as_float(bg);
            Qb[row * QST + c4 + j]  = bg;
            Qsm[row * QST + c4 + j] =
                (unsigned short)__bfloat16_as_ushort(__float2bfloat16(smv));
        }
    }

    float O[8][4];
#pragma unroll
    for (int nt = 0; nt < 8; nt++)
#pragma unroll
        for (int c = 0; c < 4; c++) O[nt][c] = 0.f;
    float m0 = -1e30f, m1 = -1e30f, l0 = 0.f, l1 = 0.f;

    const int r0 = rw + g, r1 = rw + g + 8;
    const int jt_max = (i0 + BM - 1) >> 6;

    for (int jt = 0; jt <= jt_max; jt++) {
        int j0 = jt * BN;
        __syncthreads();

        for (int t = tid; t < BN * 32; t += 512) {
            int row = t >> 5;
            int c4  = (t & 31) << 2;
            size_t goff = (((size_t)b * SS + j0 + row) * NKV + kvh) * HD + c4;
            float4 kv = *(const float4*)(Kg + goff);
            float kvals[4] = {kv.x, kv.y, kv.z, kv.w};
#pragma unroll
            for (int j = 0; j < 4; j++) {
                unsigned bg = f2tf(kvals[j]);
                float smv = kvals[j] - __uint_as_float(bg);
                Kb[row * QST + c4 + j]  = bg;
                Ksm[row * QST + c4 + j] =
                    (unsigned short)__bfloat16_as_ushort(__float2bfloat16(smv));
            }
            float4 vv = *(const float4*)(Vg + goff);
            Vt[row * VST + c4 + 0] = f2tf(vv.x);
            Vt[row * VST + c4 + 1] = f2tf(vv.y);
            Vt[row * VST + c4 + 2] = f2tf(vv.z);
            Vt[row * VST + c4 + 3] = f2tf(vv.w);
        }
        __syncthreads();

        if (j0 > i0 + rw + 15) continue;

        float sacc[4][4];
#pragma unroll
        for (int nt = 0; nt < 4; nt++)
#pragma unroll
            for (int c = 0; c < 4; c++) sacc[nt][c] = 0.f;

#pragma unroll
        for (int kk = 0; kk < HD; kk += 8) {
            unsigned ab[4], asl[4];
            ab[0] = Qb[r0 * QST + kk + tg];
            ab[1] = Qb[r1 * QST + kk + tg];
            ab[2] = Qb[r0 * QST + kk + tg + 4];
            ab[3] = Qb[r1 * QST + kk + tg + 4];
            asl[0] = ((unsigned)Qsm[r0 * QST + kk + tg]) << 16;
            asl[1] = ((unsigned)Qsm[r1 * QST + kk + tg]) << 16;
            asl[2] = ((unsigned)Qsm[r0 * QST + kk + tg + 4]) << 16;
            asl[3] = ((unsigned)Qsm[r1 * QST + kk + tg + 4]) << 16;
#pragma unroll
            for (int nt = 0; nt < 4; nt++) {
                int c = scb + nt * 8 + g;
                unsigned bb[2], bs[2];
                bb[0] = Kb[c * QST + kk + tg];
                bb[1] = Kb[c * QST + kk + tg + 4];
                bs[0] = ((unsigned)Ksm[c * QST + kk + tg]) << 16;
                bs[1] = ((unsigned)Ksm[c * QST + kk + tg + 4]) << 16;
                mma_tf32(sacc[nt], ab,  bb);
                mma_tf32(sacc[nt], asl, bb);
                mma_tf32(sacc[nt], ab,  bs);
            }
        }

        const int gr0 = i0 + r0, gr1 = i0 + r1;
        if (j0 + BN - 1 > i0 + rw) {
#pragma unroll
            for (int nt = 0; nt < 4; nt++) {
                int col = j0 + scb + nt * 8 + 2 * tg;
                if (col     > gr0) sacc[nt][0] = -1e30f;
                if (col + 1 > gr0) sacc[nt][1] = -1e30f;
                if (col     > gr1) sacc[nt][2] = -1e30f;
                if (col + 1 > gr1) sacc[nt][3] = -1e30f;
            }
        }

        float mx0 = -1e30f, mx1 = -1e30f;
#pragma unroll
        for (int nt = 0; nt < 4; nt++) {
            mx0 = fmaxf(mx0, fmaxf(sacc[nt][0], sacc[nt][1]));
            mx1 = fmaxf(mx1, fmaxf(sacc[nt][2], sacc[nt][3]));
        }
        mx0 = fmaxf(mx0, __shfl_xor_sync(0xffffffffu, mx0, 1));
        mx0 = fmaxf(mx0, __shfl_xor_sync(0xffffffffu, mx0, 2));
        mx1 = fmaxf(mx1, __shfl_xor_sync(0xffffffffu, mx1, 1));
        mx1 = fmaxf(mx1, __shfl_xor_sync(0xffffffffu, mx1, 2));
        if (tg == 0) {
            maxb[half * 128 + r0] = mx0;
            maxb[half * 128 + r1] = mx1;
        }
        barpair(1 + pair);
        mx0 = fmaxf(mx0, maxb[(half ^ 1) * 128 + r0]);
        mx1 = fmaxf(mx1, maxb[(half ^ 1) * 128 + r1]);

        float mn0 = fmaxf(m0, mx0), mn1 = fmaxf(m1, mx1);
        float al0 = __expf(m0 - mn0), al1 = __expf(m1 - mn1);

        float rs0 = 0.f, rs1 = 0.f;
#pragma unroll
        for (int nt = 0; nt < 4; nt++) {
            float p0 = __expf(sacc[nt][0] - mn0);
            float p1 = __expf(sacc[nt][1] - mn0);
            float p2 = __expf(sacc[nt][2] - mn1);
            float p3 = __expf(sacc[nt][3] - mn1);
            rs0 += p0 + p1;
            rs1 += p2 + p3;
            int colb = scb + nt * 8 + 2 * tg;
            *(uint2*)&Pt[r0 * PST + colb] = make_uint2(f2tf(p0), f2tf(p1));
            *(uint2*)&Pt[r1 * PST + colb] = make_uint2(f2tf(p2), f2tf(p3));
        }
        rs0 += __shfl_xor_sync(0xffffffffu, rs0, 1);
        rs0 += __shfl_xor_sync(0xffffffffu, rs0, 2);
        rs1 += __shfl_xor_sync(0xffffffffu, rs1, 1);
        rs1 += __shfl_xor_sync(0xffffffffu, rs1, 2);
        if (tg == 0) {
            sumb[half * 128 + r0] = rs0;
            sumb[half * 128 + r1] = rs1;
        }
        barpair(1 + pair);
        rs0 += sumb[(half ^ 1) * 128 + r0];
        rs1 += sumb[(half ^ 1) * 128 + r1];

        m0 = mn0; m1 = mn1;
        l0 = l0 * al0 + rs0;
        l1 = l1 * al1 + rs1;

#pragma unroll
        for (int nt = 0; nt < 8; nt++) {
            O[nt][0] *= al0; O[nt][1] *= al0;
            O[nt][2] *= al1; O[nt][3] *= al1;
        }

#pragma unroll
        for (int kk = 0; kk < BN; kk += 8) {
            unsigned pa[4];
            pa[0] = Pt[r0 * PST + kk + tg];
            pa[1] = Pt[r1 * PST + kk + tg];
            pa[2] = Pt[r0 * PST + kk + tg + 4];
            pa[3] = Pt[r1 * PST + kk + tg + 4];
#pragma unroll
            for (int nt = 0; nt < 8; nt++) {
                int oc = ocb + nt * 8 + g;
                unsigned vb[2];
                vb[0] = Vt[(kk + tg) * VST + oc];
                vb[1] = Vt[(kk + tg + 4) * VST + oc];
                mma_tf32(O[nt], pa, vb);
            }
        }
    }

    float inv0 = 1.f / l0, inv1 = 1.f / l1;
    size_t row0 = (size_t)b * SS + i0 + rw + g;
    size_t row1 = row0 + 8;
#pragma unroll
    for (int nt = 0; nt < 8; nt++) {
        int col = h * HD + ocb + nt * 8 + 2 * tg;
        *(float2*)(Og + row0 * (NH * HD) + col) = make_float2(
            __uint_as_float(f2tf(O[nt][0] * inv0)),
            __uint_as_float(f2tf(O[nt][1] * inv0)));
        *(float2*)(Og + row1 * (NH * HD) + col) = make_float2(
            __uint_as_float(f2tf(O[nt][2] * inv1)),
            __uint_as_float(f2tf(O[nt][3] * inv1)));
    }
}

// ---------------------------------------------------------------------------
// Launch.
// ---------------------------------------------------------------------------
extern "C" void kernel_launch(void* const* d_in, const int* in_sizes, int n_in,
                              void* d_out, int out_size)
{
    const float* x  = (const float*)d_in[0];
    const float* fc = (const float*)d_in[2];
    const float* fs = (const float*)d_in[3];
    const float* wq = (const float*)d_in[6];
    const float* wk = (const float*)d_in[7];
    const float* wv = (const float*)d_in[8];
    const float* wo = (const float*)d_in[9];
    float* out = (float*)d_out;

    float *q, *k, *v, *attn, *xr, *wqr, *wkr, *wvr, *wor;
    cudaGetSymbolAddress((void**)&q, g_q);
    cudaGetSymbolAddress((void**)&k, g_k);
    cudaGetSymbolAddress((void**)&v, g_v);
    cudaGetSymbolAddress((void**)&attn, g_attn);
    cudaGetSymbolAddress((void**)&xr, g_xr);
    cudaGetSymbolAddress((void**)&wqr, g_wqr);
    cudaGetSymbolAddress((void**)&wkr, g_wkr);
    cudaGetSymbolAddress((void**)&wvr, g_wvr);
    cudaGetSymbolAddress((void**)&wor, g_wor);

    const int M = BB * SS;  // 4096

    int nx = BB * SS * DIM;
    int nq = DIM * NH * HD;
    int nk = DIM * NKV * HD;
    round_tf32_kernel<<<nx / 1024, 256>>>(x, xr, nx);
    round_tf32_kernel<<<nq / 1024, 256>>>(wq, wqr, nq);
    round_tf32_kernel<<<nk / 1024, 256>>>(wk, wkr, nk);
    round_tf32_kernel<<<nk / 1024, 256>>>(wv, wvr, nk);
    round_tf32_kernel<<<nq / 1024, 256>>>(wo, wor, nq);

    cudaFuncSetAttribute(gemm_tf32,
                         cudaFuncAttributeMaxDynamicSharedMemorySize, GEMM_SMEM);

    gemm_tf32<<<dim3(NH * HD / 128, M / 128), 256, GEMM_SMEM>>>(xr, wqr, q, M, NH * HD, DIM);
    gemm_tf32<<<dim3(NKV * HD / 128, M / 128), 256, GEMM_SMEM>>>(xr, wkr, k, M, NKV * HD, DIM);
    gemm_tf32<<<dim3(NKV * HD / 128, M / 128), 256, GEMM_SMEM>>>(xr, wvr, v, M, NKV * HD, DIM);

    int qtot = BB * SS * NH * (HD / 2);
    int ktot = BB * SS * NKV * (HD / 2);
    rope_kernel<<<(qtot + 255) / 256, 256>>>(q, fc, fs, NH, qtot);
    rope_kernel<<<(ktot + 255) / 256, 256>>>(k, fc, fs, NKV, ktot);

    cudaFuncSetAttribute(attn_mma,
                         cudaFuncAttributeMaxDynamicSharedMemorySize, ATTN_SMEM);
    attn_mma<<<dim3(SS / BM, NH, BB), 512, ATTN_SMEM>>>(q, k, v, attn);

    gemm_tf32<<<dim3(DIM / 128, M / 128), 256, GEMM_SMEM>>>(attn, wor, out, M, DIM, DIM);
}